// round 10
// baseline (speedup 1.0000x reference)
#include <cuda_runtime.h>
#include <cuda_fp16.h>
#include <cstdint>

#define BATCH   524288
#define DIM     64
#define NE      8
#define NH      64
#define GHID    32

#define TILE_M  128
#define NTILES  (BATCH / TILE_M)   // 4096
#define GRID    296                // 2 CTAs per SM
#define THREADS 256
#define NSUB    8

// ---------------- smem byte layout ----------------
#define OFF_XHI    0        // fp16 [128][64] SW128 = 16384
#define OFF_GW1    16384    // fp32 [32][32] = 4096
#define OFF_GW2    20480    // fp32 [32][8] = 1024
#define OFF_GB1    21504    // fp32 [32] = 128
#define OFF_GB2    21632    // fp32 [8] = 32
#define OFF_PROB   21664    // fp32 [128][9] = 4608 (pitch 9, conflict-free)
#define OFF_EO     26272    // fp32 [128][9] = 4608
#define OFF_BW     30880    // float4 [8][8][4]: {b1 pair, w2 pair} = 4096
#define SMEM_BYTES 34976

#define SW(o) ((o) ^ (((o) >> 3) & 0x70))

static __device__ __forceinline__ uint32_t smem_u32(const void* p) {
    uint32_t a;
    asm("{ .reg .u64 t; cvta.to.shared.u64 t, %1; cvt.u32.u64 %0, t; }" : "=r"(a) : "l"(p));
    return a;
}
static __device__ __forceinline__ void ldsm4(uint32_t* r, uint32_t addr) {
    asm volatile("ldmatrix.sync.aligned.m8n8.x4.shared.b16 {%0,%1,%2,%3}, [%4];"
                 : "=r"(r[0]), "=r"(r[1]), "=r"(r[2]), "=r"(r[3]) : "r"(addr));
}
static __device__ __forceinline__ void mma16816(float* c, const uint32_t* a,
                                                uint32_t b0, uint32_t b1) {
    asm volatile(
        "mma.sync.aligned.m16n8k16.row.col.f32.f16.f16.f32 "
        "{%0,%1,%2,%3}, {%4,%5,%6,%7}, {%8,%9}, {%0,%1,%2,%3};"
        : "+f"(c[0]), "+f"(c[1]), "+f"(c[2]), "+f"(c[3])
        : "r"(a[0]), "r"(a[1]), "r"(a[2]), "r"(a[3]), "r"(b0), "r"(b1));
}

typedef unsigned long long ull;
static __device__ __forceinline__ ull fma2(ull a, ull b, ull c) {
    ull d;
    asm("fma.rn.f32x2 %0, %1, %2, %3;" : "=l"(d) : "l"(a), "l"(b), "l"(c));
    return d;
}
static __device__ __forceinline__ ull pack2(float x, float y) {
    ull d;
    asm("mov.b64 %0, {%1, %2};" : "=l"(d) : "f"(x), "f"(y));
    return d;
}
static __device__ __forceinline__ void unpack2(ull v, float& x, float& y) {
    asm("mov.b64 {%0, %1}, %2;" : "=f"(x), "=f"(y) : "l"(v));
}
static __device__ __forceinline__ uint32_t packh2(float a, float b) {
    __half ha = __float2half_rn(a), hb = __float2half_rn(b);
    return ((uint32_t)__half_as_ushort(hb) << 16) | __half_as_ushort(ha);
}
static __device__ __forceinline__ uint32_t cvth2(float a, float b) {
    uint32_t r;
    asm("cvt.rn.f16x2.f32 %0, %1, %2;" : "=r"(r) : "f"(b), "f"(a));
    return r;
}

__global__ void __launch_bounds__(THREADS, 2)
moe_mma_kernel(const float* __restrict__ A,   const float* __restrict__ S,
               const float* __restrict__ gw1, const float* __restrict__ gb1,
               const float* __restrict__ gw2, const float* __restrict__ gb2,
               const float* __restrict__ ew1, const float* __restrict__ eb1,
               const float* __restrict__ ew2, const float* __restrict__ eb2,
               float* __restrict__ out)
{
    extern __shared__ char smem[];
    float* smf = (float*)smem;
    const uint32_t sbase = smem_u32(smem);
    const int tid  = threadIdx.x;
    const int lane = tid & 31;
    const int wid  = tid >> 5;          // warp == expert id

    // ---- stage small fp32 weights ----
    for (int i = tid; i < GHID * GHID; i += THREADS) smf[OFF_GW1 / 4 + i] = gw1[i];
    for (int i = tid; i < GHID * NE;   i += THREADS) smf[OFF_GW2 / 4 + i] = gw2[i];
    if (tid < GHID) smf[OFF_GB1 / 4 + tid] = gb1[tid];
    if (tid < NE)   smf[OFF_GB2 / 4 + tid] = gb2[tid];
    // combined epilogue buffer: BW[e][nf][q] = {b1[2q], b1[2q+1], w2[2q], w2[2q+1]} at col nf*8+2q
    for (int i = tid; i < NE * 8 * 4; i += THREADS) {
        int e = i >> 5, nf = (i >> 2) & 7, q = i & 3;
        int col = nf * 8 + q * 2;
        float4 v;
        v.x = eb1[e * NH + col];     v.y = eb1[e * NH + col + 1];
        v.z = ew2[e * NH + col];     v.w = ew2[e * NH + col + 1];
        ((float4*)(smem + OFF_BW))[i] = v;
    }
    const float b2v = eb2[wid];

    // ---- expert W1 B-fragments in registers (fp16, single rounding) ----
    uint32_t bh[8][4][2];
    {
        const float* we = ew1 + wid * DIM * NH;
        const int n  = (lane >> 2);
        const int kb = (lane & 3) * 2;
        #pragma unroll
        for (int nf = 0; nf < 8; nf++) {
            #pragma unroll
            for (int kk = 0; kk < 4; kk++) {
                const int k0 = kk * 16 + kb;
                bh[nf][kk][0] = packh2(we[(k0 + 0) * NH + nf * 8 + n],
                                       we[(k0 + 1) * NH + nf * 8 + n]);
                bh[nf][kk][1] = packh2(we[(k0 + 8) * NH + nf * 8 + n],
                                       we[(k0 + 9) * NH + nf * 8 + n]);
            }
        }
    }
    __syncthreads();

    const int rl = (lane & 7) + ((lane >> 3) & 1) * 8;
    const uint32_t pb  = (uint32_t)(rl * 128 + ((lane >> 4) * 16));
    const uint32_t swt = ((uint32_t)(rl * 128) >> 3) & 0x70;
    const float4* bwp = (const float4*)(smem + OFF_BW) + wid * 32 + (lane & 3);

    for (int tile = blockIdx.x; tile < NTILES; tile += GRID) {
        const int rowBase = tile * TILE_M;

        // ---- convert: all 256 threads, LDG.128 -> fp16 -> SW128 XHI ----
        #pragma unroll
        for (int w = 0; w < 8; w++) {
            int i = tid + w * THREADS;          // 0..2047
            int row = i >> 4, c4 = i & 15;
            const float4* src = (c4 < 8)
                ? (const float4*)(A + (rowBase + row) * 32) + c4
                : (const float4*)(S + (rowBase + row) * 32) + (c4 - 8);
            float4 v = *src;
            uint2 hp;
            hp.x = cvth2(v.x, v.y);
            hp.y = cvth2(v.z, v.w);
            *(uint2*)(smem + OFF_XHI + SW((uint32_t)(row * 128 + c4 * 8))) = hp;
        }
        __syncthreads();   // barrier 1: XHI ready

        // ---- gating (warps 0-3 only, overlaps with warps 4-7 GEMM) ----
        if (tid < TILE_M) {
            const float4* srow = (const float4*)(S + (rowBase + tid) * 32);
            ull h2[16];
            #pragma unroll
            for (int p = 0; p < 16; p++)
                h2[p] = *(const ull*)(smf + OFF_GB1 / 4 + 2 * p);
            #pragma unroll
            for (int kc = 0; kc < 4; kc++) {
                float4 va = srow[kc * 2], vb = srow[kc * 2 + 1];
                float sv[8] = {va.x, va.y, va.z, va.w, vb.x, vb.y, vb.z, vb.w};
                #pragma unroll
                for (int kj = 0; kj < 8; kj++) {
                    int k = kc * 8 + kj;
                    ull s2 = pack2(sv[kj], sv[kj]);
                    const ulonglong2* wr = (const ulonglong2*)(smem + OFF_GW1 + k * 128);
                    #pragma unroll
                    for (int j = 0; j < 8; j++) {
                        ulonglong2 w = wr[j];
                        h2[2 * j]     = fma2(s2, w.x, h2[2 * j]);
                        h2[2 * j + 1] = fma2(s2, w.y, h2[2 * j + 1]);
                    }
                }
            }
            ull l2[4];
            {
                ulonglong2 b = *(const ulonglong2*)(smem + OFF_GB2);
                l2[0] = b.x; l2[1] = b.y;
                b = *(const ulonglong2*)(smem + OFF_GB2 + 16);
                l2[2] = b.x; l2[3] = b.y;
            }
            #pragma unroll
            for (int p = 0; p < 16; p++) {
                float a, b; unpack2(h2[p], a, b);
                a = fmaxf(a, 0.f); b = fmaxf(b, 0.f);
                ull pa = pack2(a, a), pb2 = pack2(b, b);
                ulonglong2 wa0 = *(const ulonglong2*)(smem + OFF_GW2 + (2 * p) * 32);
                ulonglong2 wa1 = *(const ulonglong2*)(smem + OFF_GW2 + (2 * p) * 32 + 16);
                ulonglong2 wb0 = *(const ulonglong2*)(smem + OFF_GW2 + (2 * p + 1) * 32);
                ulonglong2 wb1 = *(const ulonglong2*)(smem + OFF_GW2 + (2 * p + 1) * 32 + 16);
                l2[0] = fma2(pa, wa0.x, l2[0]); l2[1] = fma2(pa, wa0.y, l2[1]);
                l2[2] = fma2(pa, wa1.x, l2[2]); l2[3] = fma2(pa, wa1.y, l2[3]);
                l2[0] = fma2(pb2, wb0.x, l2[0]); l2[1] = fma2(pb2, wb0.y, l2[1]);
                l2[2] = fma2(pb2, wb1.x, l2[2]); l2[3] = fma2(pb2, wb1.y, l2[3]);
            }
            float logit[NE];
            #pragma unroll
            for (int e2 = 0; e2 < 4; e2++) unpack2(l2[e2], logit[2 * e2], logit[2 * e2 + 1]);
            float mx = logit[0];
            #pragma unroll
            for (int e = 1; e < NE; e++) mx = fmaxf(mx, logit[e]);
            float se = 0.f, pr[NE];
            #pragma unroll
            for (int e = 0; e < NE; e++) { pr[e] = __expf(logit[e] - mx); se += pr[e]; }
            float inv = __fdividef(1.f, se);
            #pragma unroll
            for (int e = 0; e < NE; e++) smf[OFF_PROB / 4 + tid * 9 + e] = pr[e] * inv;
        }

        // ---- expert GEMM: single fp16 product, warp = expert ----
        #pragma unroll 1
        for (int sub = 0; sub < NSUB; sub++) {
            float c[8][4];
            float w2r[8][2];
            #pragma unroll
            for (int nf = 0; nf < 8; nf++) {
                float4 bw = bwp[nf * 4];
                c[nf][0] = bw.x; c[nf][1] = bw.y; c[nf][2] = bw.x; c[nf][3] = bw.y;
                w2r[nf][0] = bw.z; w2r[nf][1] = bw.w;
            }
            #pragma unroll
            for (int kk = 0; kk < 4; kk++) {
                uint32_t ah[4];
                uint32_t off = (uint32_t)(sub * 2048) + ((pb + kk * 32) ^ swt);
                ldsm4(ah, sbase + OFF_XHI + off);
                #pragma unroll
                for (int nf = 0; nf < 8; nf++) mma16816(c[nf], ah, bh[nf][kk][0], bh[nf][kk][1]);
            }
            float p0 = 0.f, p1 = 0.f;
            #pragma unroll
            for (int nf = 0; nf < 8; nf++) {
                p0 = fmaf(fmaxf(c[nf][0], 0.f), w2r[nf][0], p0);
                p0 = fmaf(fmaxf(c[nf][1], 0.f), w2r[nf][1], p0);
                p1 = fmaf(fmaxf(c[nf][2], 0.f), w2r[nf][0], p1);
                p1 = fmaf(fmaxf(c[nf][3], 0.f), w2r[nf][1], p1);
            }
            p0 += __shfl_xor_sync(0xFFFFFFFFu, p0, 1);
            p0 += __shfl_xor_sync(0xFFFFFFFFu, p0, 2);
            p1 += __shfl_xor_sync(0xFFFFFFFFu, p1, 1);
            p1 += __shfl_xor_sync(0xFFFFFFFFu, p1, 2);
            if ((lane & 3) == 0) {
                int r = sub * 16 + (lane >> 2);
                smf[OFF_EO / 4 + r * 9 + wid]       = p0 + b2v;
                smf[OFF_EO / 4 + (r + 8) * 9 + wid] = p1 + b2v;
            }
        }
        __syncthreads();   // barrier 2: EO + PROB ready

        // ---- final: weighted sum over experts ----
        if (tid < TILE_M) {
            const float* pr = smf + OFF_PROB / 4 + tid * 9;
            const float* eo = smf + OFF_EO / 4 + tid * 9;
            float r = 0.f;
            #pragma unroll
            for (int e = 0; e < NE; e++) r = fmaf(pr[e], eo[e], r);
            out[rowBase + tid] = r;
        }
    }
}

extern "C" void kernel_launch(void* const* d_in, const int* in_sizes, int n_in,
                              void* d_out, int out_size)
{
    (void)in_sizes; (void)n_in; (void)out_size;
    const float* A   = (const float*)d_in[0];
    const float* S   = (const float*)d_in[1];
    const float* gw1 = (const float*)d_in[2];
    const float* gb1 = (const float*)d_in[3];
    const float* gw2 = (const float*)d_in[4];
    const float* gb2 = (const float*)d_in[5];
    const float* ew1 = (const float*)d_in[6];
    const float* eb1 = (const float*)d_in[7];
    const float* ew2 = (const float*)d_in[8];
    const float* eb2 = (const float*)d_in[9];
    float* out = (float*)d_out;

    cudaFuncSetAttribute(moe_mma_kernel, cudaFuncAttributeMaxDynamicSharedMemorySize, SMEM_BYTES);
    moe_mma_kernel<<<GRID, THREADS, SMEM_BYTES>>>(
        A, S, gw1, gb1, gw2, gb2, ew1, eb1, ew2, eb2, out);
}

// round 11
// speedup vs baseline: 1.0170x; 1.0170x over previous
#include <cuda_runtime.h>
#include <cuda_fp16.h>
#include <cstdint>

#define BATCH   524288
#define DIM     64
#define NE      8
#define NH      64
#define GHID    32

#define TILE_M  128
#define NTILES  (BATCH / TILE_M)   // 4096
#define GRID    296                // 2 CTAs per SM
#define THREADS 256
#define NSUB    8

// ---------------- smem byte layout ----------------
#define OFF_XHI    0        // fp16 [128][64] SW128 = 16384 ([A 32 | S 32] per row)
#define OFF_GW1    16384    // fp32 [32][32] = 4096
#define OFF_GW2    20480    // fp32 [32][8] = 1024
#define OFF_GB1    21504    // fp32 [32] = 128
#define OFF_GB2    21632    // fp32 [8] = 32
#define OFF_PROB   21664    // fp32 [128][9] = 4608 (pitch 9, conflict-free)
#define OFF_EO     26272    // fp32 [128][9] = 4608
#define OFF_BW     30880    // float4 [8][8][4]: {b1 pair, w2 pair} = 4096
#define SMEM_BYTES 34976

#define SW(o) ((o) ^ (((o) >> 3) & 0x70))

static __device__ __forceinline__ uint32_t smem_u32(const void* p) {
    uint32_t a;
    asm("{ .reg .u64 t; cvta.to.shared.u64 t, %1; cvt.u32.u64 %0, t; }" : "=r"(a) : "l"(p));
    return a;
}
static __device__ __forceinline__ void ldsm4(uint32_t* r, uint32_t addr) {
    asm volatile("ldmatrix.sync.aligned.m8n8.x4.shared.b16 {%0,%1,%2,%3}, [%4];"
                 : "=r"(r[0]), "=r"(r[1]), "=r"(r[2]), "=r"(r[3]) : "r"(addr));
}
static __device__ __forceinline__ void mma16816(float* c, const uint32_t* a,
                                                uint32_t b0, uint32_t b1) {
    asm volatile(
        "mma.sync.aligned.m16n8k16.row.col.f32.f16.f16.f32 "
        "{%0,%1,%2,%3}, {%4,%5,%6,%7}, {%8,%9}, {%0,%1,%2,%3};"
        : "+f"(c[0]), "+f"(c[1]), "+f"(c[2]), "+f"(c[3])
        : "r"(a[0]), "r"(a[1]), "r"(a[2]), "r"(a[3]), "r"(b0), "r"(b1));
}

typedef unsigned long long ull;
static __device__ __forceinline__ ull fma2(ull a, ull b, ull c) {
    ull d;
    asm("fma.rn.f32x2 %0, %1, %2, %3;" : "=l"(d) : "l"(a), "l"(b), "l"(c));
    return d;
}
static __device__ __forceinline__ ull pack2(float x, float y) {
    ull d;
    asm("mov.b64 %0, {%1, %2};" : "=l"(d) : "f"(x), "f"(y));
    return d;
}
static __device__ __forceinline__ void unpack2(ull v, float& x, float& y) {
    asm("mov.b64 {%0, %1}, %2;" : "=f"(x), "=f"(y) : "l"(v));
}
static __device__ __forceinline__ uint32_t packh2(float a, float b) {
    __half ha = __float2half_rn(a), hb = __float2half_rn(b);
    return ((uint32_t)__half_as_ushort(hb) << 16) | __half_as_ushort(ha);
}
static __device__ __forceinline__ uint32_t cvth2(float a, float b) {
    uint32_t r;
    asm("cvt.rn.f16x2.f32 %0, %1, %2;" : "=r"(r) : "f"(b), "f"(a));
    return r;
}

__global__ void __launch_bounds__(THREADS, 2)
moe_mma_kernel(const float* __restrict__ A,   const float* __restrict__ S,
               const float* __restrict__ gw1, const float* __restrict__ gb1,
               const float* __restrict__ gw2, const float* __restrict__ gb2,
               const float* __restrict__ ew1, const float* __restrict__ eb1,
               const float* __restrict__ ew2, const float* __restrict__ eb2,
               float* __restrict__ out)
{
    extern __shared__ char smem[];
    float* smf = (float*)smem;
    const uint32_t sbase = smem_u32(smem);
    const int tid  = threadIdx.x;
    const int lane = tid & 31;
    const int wid  = tid >> 5;          // warp == expert id

    // ---- stage small fp32 weights ----
    for (int i = tid; i < GHID * GHID; i += THREADS) smf[OFF_GW1 / 4 + i] = gw1[i];
    for (int i = tid; i < GHID * NE;   i += THREADS) smf[OFF_GW2 / 4 + i] = gw2[i];
    if (tid < GHID) smf[OFF_GB1 / 4 + tid] = gb1[tid];
    if (tid < NE)   smf[OFF_GB2 / 4 + tid] = gb2[tid];
    // combined epilogue buffer: BW[e][nf][q] = {b1 pair, w2 pair} for col nf*8+2q
    for (int i = tid; i < NE * 8 * 4; i += THREADS) {
        int e = i >> 5, nf = (i >> 2) & 7, q = i & 3;
        int col = nf * 8 + q * 2;
        float4 v;
        v.x = eb1[e * NH + col];     v.y = eb1[e * NH + col + 1];
        v.z = ew2[e * NH + col];     v.w = ew2[e * NH + col + 1];
        ((float4*)(smem + OFF_BW))[i] = v;
    }
    const float b2v = eb2[wid];

    // ---- expert W1 B-fragments in registers (fp16, single rounding) ----
    uint32_t bh[8][4][2];
    {
        const float* we = ew1 + wid * DIM * NH;
        const int n  = (lane >> 2);
        const int kb = (lane & 3) * 2;
        #pragma unroll
        for (int nf = 0; nf < 8; nf++) {
            #pragma unroll
            for (int kk = 0; kk < 4; kk++) {
                const int k0 = kk * 16 + kb;
                bh[nf][kk][0] = packh2(we[(k0 + 0) * NH + nf * 8 + n],
                                       we[(k0 + 1) * NH + nf * 8 + n]);
                bh[nf][kk][1] = packh2(we[(k0 + 8) * NH + nf * 8 + n],
                                       we[(k0 + 9) * NH + nf * 8 + n]);
            }
        }
    }
    __syncthreads();

    const int rl = (lane & 7) + ((lane >> 3) & 1) * 8;
    const uint32_t pb  = (uint32_t)(rl * 128 + ((lane >> 4) * 16));
    const uint32_t swt = ((uint32_t)(rl * 128) >> 3) & 0x70;
    const float4* bwp = (const float4*)(smem + OFF_BW) + wid * 32 + (lane & 3);

    for (int tile = blockIdx.x; tile < NTILES; tile += GRID) {
        const int rowBase = tile * TILE_M;

        // ---- convert: all 256 threads, coalesced LDG.128 -> fp16 -> SW128 XHI ----
        #pragma unroll
        for (int w = 0; w < 8; w++) {
            int i = tid + w * THREADS;          // 0..2047
            int row = i >> 4, c4 = i & 15;
            const float4* src = (c4 < 8)
                ? (const float4*)(A + (rowBase + row) * 32) + c4
                : (const float4*)(S + (rowBase + row) * 32) + (c4 - 8);
            float4 v = *src;
            uint2 hp;
            hp.x = cvth2(v.x, v.y);
            hp.y = cvth2(v.z, v.w);
            *(uint2*)(smem + OFF_XHI + SW((uint32_t)(row * 128 + c4 * 8))) = hp;
        }
        __syncthreads();   // barrier 1: XHI ready

        // ---- gating (warps 0-3): S read back from XHI (fp16), fp32 math ----
        if (tid < TILE_M) {
            ull h2[16];
            #pragma unroll
            for (int p = 0; p < 16; p++)
                h2[p] = *(const ull*)(smf + OFF_GB1 / 4 + 2 * p);
            #pragma unroll
            for (int j = 0; j < 4; j++) {
                // this row's S fp16 values k = 8j..8j+7 (bytes 64+16j of the row line)
                uint4 q = *(const uint4*)(smem + OFF_XHI +
                                          SW((uint32_t)(tid * 128 + 64 + j * 16)));
                uint32_t qs[4] = {q.x, q.y, q.z, q.w};
                #pragma unroll
                for (int u = 0; u < 4; u++) {
                    float2 f = __half22float2(*(const __half2*)&qs[u]);
                    #pragma unroll
                    for (int v2 = 0; v2 < 2; v2++) {
                        int k = j * 8 + u * 2 + v2;
                        float sv = v2 ? f.y : f.x;
                        ull s2 = pack2(sv, sv);
                        const ulonglong2* wr =
                            (const ulonglong2*)(smem + OFF_GW1 + k * 128);
                        #pragma unroll
                        for (int jj = 0; jj < 8; jj++) {
                            ulonglong2 w = wr[jj];
                            h2[2 * jj]     = fma2(s2, w.x, h2[2 * jj]);
                            h2[2 * jj + 1] = fma2(s2, w.y, h2[2 * jj + 1]);
                        }
                    }
                }
            }
            ull l2[4];
            {
                ulonglong2 b = *(const ulonglong2*)(smem + OFF_GB2);
                l2[0] = b.x; l2[1] = b.y;
                b = *(const ulonglong2*)(smem + OFF_GB2 + 16);
                l2[2] = b.x; l2[3] = b.y;
            }
            #pragma unroll
            for (int p = 0; p < 16; p++) {
                float a, b; unpack2(h2[p], a, b);
                a = fmaxf(a, 0.f); b = fmaxf(b, 0.f);
                ull pa = pack2(a, a), pb2 = pack2(b, b);
                ulonglong2 wa0 = *(const ulonglong2*)(smem + OFF_GW2 + (2 * p) * 32);
                ulonglong2 wa1 = *(const ulonglong2*)(smem + OFF_GW2 + (2 * p) * 32 + 16);
                ulonglong2 wb0 = *(const ulonglong2*)(smem + OFF_GW2 + (2 * p + 1) * 32);
                ulonglong2 wb1 = *(const ulonglong2*)(smem + OFF_GW2 + (2 * p + 1) * 32 + 16);
                l2[0] = fma2(pa, wa0.x, l2[0]); l2[1] = fma2(pa, wa0.y, l2[1]);
                l2[2] = fma2(pa, wa1.x, l2[2]); l2[3] = fma2(pa, wa1.y, l2[3]);
                l2[0] = fma2(pb2, wb0.x, l2[0]); l2[1] = fma2(pb2, wb0.y, l2[1]);
                l2[2] = fma2(pb2, wb1.x, l2[2]); l2[3] = fma2(pb2, wb1.y, l2[3]);
            }
            float logit[NE];
            #pragma unroll
            for (int e2 = 0; e2 < 4; e2++) unpack2(l2[e2], logit[2 * e2], logit[2 * e2 + 1]);
            float mx = logit[0];
            #pragma unroll
            for (int e = 1; e < NE; e++) mx = fmaxf(mx, logit[e]);
            float se = 0.f, pr[NE];
            #pragma unroll
            for (int e = 0; e < NE; e++) { pr[e] = __expf(logit[e] - mx); se += pr[e]; }
            float inv = __fdividef(1.f, se);
            #pragma unroll
            for (int e = 0; e < NE; e++) smf[OFF_PROB / 4 + tid * 9 + e] = pr[e] * inv;
        }

        // ---- expert GEMM: single fp16 product, warp = expert ----
        #pragma unroll 1
        for (int sub = 0; sub < NSUB; sub++) {
            float c[8][4];
            float w2r[8][2];
            #pragma unroll
            for (int nf = 0; nf < 8; nf++) {
                float4 bw = bwp[nf * 4];
                c[nf][0] = bw.x; c[nf][1] = bw.y; c[nf][2] = bw.x; c[nf][3] = bw.y;
                w2r[nf][0] = bw.z; w2r[nf][1] = bw.w;
            }
            #pragma unroll
            for (int kk = 0; kk < 4; kk++) {
                uint32_t ah[4];
                uint32_t off = (uint32_t)(sub * 2048) + ((pb + kk * 32) ^ swt);
                ldsm4(ah, sbase + OFF_XHI + off);
                #pragma unroll
                for (int nf = 0; nf < 8; nf++) mma16816(c[nf], ah, bh[nf][kk][0], bh[nf][kk][1]);
            }
            float p0 = 0.f, p1 = 0.f;
            #pragma unroll
            for (int nf = 0; nf < 8; nf++) {
                p0 = fmaf(fmaxf(c[nf][0], 0.f), w2r[nf][0], p0);
                p0 = fmaf(fmaxf(c[nf][1], 0.f), w2r[nf][1], p0);
                p1 = fmaf(fmaxf(c[nf][2], 0.f), w2r[nf][0], p1);
                p1 = fmaf(fmaxf(c[nf][3], 0.f), w2r[nf][1], p1);
            }
            p0 += __shfl_xor_sync(0xFFFFFFFFu, p0, 1);
            p0 += __shfl_xor_sync(0xFFFFFFFFu, p0, 2);
            p1 += __shfl_xor_sync(0xFFFFFFFFu, p1, 1);
            p1 += __shfl_xor_sync(0xFFFFFFFFu, p1, 2);
            if ((lane & 3) == 0) {
                int r = sub * 16 + (lane >> 2);
                smf[OFF_EO / 4 + r * 9 + wid]       = p0 + b2v;
                smf[OFF_EO / 4 + (r + 8) * 9 + wid] = p1 + b2v;
            }
        }
        __syncthreads();   // barrier 2: EO + PROB ready

        // ---- final: weighted sum over experts ----
        if (tid < TILE_M) {
            const float* pr = smf + OFF_PROB / 4 + tid * 9;
            const float* eo = smf + OFF_EO / 4 + tid * 9;
            float r = 0.f;
            #pragma unroll
            for (int e = 0; e < NE; e++) r = fmaf(pr[e], eo[e], r);
            out[rowBase + tid] = r;
        }
    }
}

extern "C" void kernel_launch(void* const* d_in, const int* in_sizes, int n_in,
                              void* d_out, int out_size)
{
    (void)in_sizes; (void)n_in; (void)out_size;
    const float* A   = (const float*)d_in[0];
    const float* S   = (const float*)d_in[1];
    const float* gw1 = (const float*)d_in[2];
    const float* gb1 = (const float*)d_in[3];
    const float* gw2 = (const float*)d_in[4];
    const float* gb2 = (const float*)d_in[5];
    const float* ew1 = (const float*)d_in[6];
    const float* eb1 = (const float*)d_in[7];
    const float* ew2 = (const float*)d_in[8];
    const float* eb2 = (const float*)d_in[9];
    float* out = (float*)d_out;

    cudaFuncSetAttribute(moe_mma_kernel, cudaFuncAttributeMaxDynamicSharedMemorySize, SMEM_BYTES);
    moe_mma_kernel<<<GRID, THREADS, SMEM_BYTES>>>(
        A, S, gw1, gb1, gw2, gb2, ew1, eb1, ew2, eb2, out);
}

// round 12
// speedup vs baseline: 1.0383x; 1.0210x over previous
#include <cuda_runtime.h>
#include <cuda_fp16.h>
#include <cstdint>

#define BATCH   524288
#define DIM     64
#define NE      8
#define NH      64
#define GHID    32

#define TILE_M  128
#define NTILES  (BATCH / TILE_M)   // 4096
#define GRID    296                // 2 CTAs per SM
#define THREADS 256
#define NSUB    8

// ---------------- smem byte layout ----------------
#define OFF_XHI    0        // fp16 [128][64] SW128 = 16384
#define OFF_ST     16384    // fp32 S transposed [32][129] = 16512
#define OFF_GW1    32896    // fp32 [32][32] = 4096
#define OFF_GW2    36992    // fp32 [32][8] = 1024
#define OFF_GB1    38016    // fp32 [32] = 128
#define OFF_GB2    38144    // fp32 [8] = 32
#define OFF_PROB   38176    // fp32 [128][9] = 4608 (pitch 9, conflict-free)
#define OFF_EO     42784    // fp32 [128][9] = 4608
#define OFF_BW     47392    // float4 [8][8][4]: {b1 pair, w2 pair} = 4096
#define SMEM_BYTES 51488

#define SW(o) ((o) ^ (((o) >> 3) & 0x70))

static __device__ __forceinline__ uint32_t smem_u32(const void* p) {
    uint32_t a;
    asm("{ .reg .u64 t; cvta.to.shared.u64 t, %1; cvt.u32.u64 %0, t; }" : "=r"(a) : "l"(p));
    return a;
}
static __device__ __forceinline__ void ldsm4(uint32_t* r, uint32_t addr) {
    asm volatile("ldmatrix.sync.aligned.m8n8.x4.shared.b16 {%0,%1,%2,%3}, [%4];"
                 : "=r"(r[0]), "=r"(r[1]), "=r"(r[2]), "=r"(r[3]) : "r"(addr));
}
static __device__ __forceinline__ void mma16816(float* c, const uint32_t* a,
                                                uint32_t b0, uint32_t b1) {
    asm volatile(
        "mma.sync.aligned.m16n8k16.row.col.f32.f16.f16.f32 "
        "{%0,%1,%2,%3}, {%4,%5,%6,%7}, {%8,%9}, {%0,%1,%2,%3};"
        : "+f"(c[0]), "+f"(c[1]), "+f"(c[2]), "+f"(c[3])
        : "r"(a[0]), "r"(a[1]), "r"(a[2]), "r"(a[3]), "r"(b0), "r"(b1));
}

typedef unsigned long long ull;
static __device__ __forceinline__ ull fma2(ull a, ull b, ull c) {
    ull d;
    asm("fma.rn.f32x2 %0, %1, %2, %3;" : "=l"(d) : "l"(a), "l"(b), "l"(c));
    return d;
}
static __device__ __forceinline__ ull pack2(float x, float y) {
    ull d;
    asm("mov.b64 %0, {%1, %2};" : "=l"(d) : "f"(x), "f"(y));
    return d;
}
static __device__ __forceinline__ void unpack2(ull v, float& x, float& y) {
    asm("mov.b64 {%0, %1}, %2;" : "=f"(x), "=f"(y) : "l"(v));
}
static __device__ __forceinline__ uint32_t packh2(float a, float b) {
    __half ha = __float2half_rn(a), hb = __float2half_rn(b);
    return ((uint32_t)__half_as_ushort(hb) << 16) | __half_as_ushort(ha);
}
static __device__ __forceinline__ uint32_t cvth2(float a, float b) {
    uint32_t r;
    asm("cvt.rn.f16x2.f32 %0, %1, %2;" : "=r"(r) : "f"(b), "f"(a));
    return r;
}

__global__ void __launch_bounds__(THREADS, 2)
moe_mma_kernel(const float* __restrict__ A,   const float* __restrict__ S,
               const float* __restrict__ gw1, const float* __restrict__ gb1,
               const float* __restrict__ gw2, const float* __restrict__ gb2,
               const float* __restrict__ ew1, const float* __restrict__ eb1,
               const float* __restrict__ ew2, const float* __restrict__ eb2,
               float* __restrict__ out)
{
    extern __shared__ char smem[];
    float* smf = (float*)smem;
    const uint32_t sbase = smem_u32(smem);
    const int tid  = threadIdx.x;
    const int lane = tid & 31;
    const int wid  = tid >> 5;          // warp == expert id

    // ---- stage small fp32 weights ----
    for (int i = tid; i < GHID * GHID; i += THREADS) smf[OFF_GW1 / 4 + i] = gw1[i];
    for (int i = tid; i < GHID * NE;   i += THREADS) smf[OFF_GW2 / 4 + i] = gw2[i];
    if (tid < GHID) smf[OFF_GB1 / 4 + tid] = gb1[tid];
    if (tid < NE)   smf[OFF_GB2 / 4 + tid] = gb2[tid];
    // combined epilogue buffer: BW[e][nf][q] = {b1 pair, w2 pair} for col nf*8+2q
    for (int i = tid; i < NE * 8 * 4; i += THREADS) {
        int e = i >> 5, nf = (i >> 2) & 7, q = i & 3;
        int col = nf * 8 + q * 2;
        float4 v;
        v.x = eb1[e * NH + col];     v.y = eb1[e * NH + col + 1];
        v.z = ew2[e * NH + col];     v.w = ew2[e * NH + col + 1];
        ((float4*)(smem + OFF_BW))[i] = v;
    }
    const float b2v = eb2[wid];

    // ---- expert W1 B-fragments in registers (fp16, single rounding) ----
    uint32_t bh[8][4][2];
    {
        const float* we = ew1 + wid * DIM * NH;
        const int n  = (lane >> 2);
        const int kb = (lane & 3) * 2;
        #pragma unroll
        for (int nf = 0; nf < 8; nf++) {
            #pragma unroll
            for (int kk = 0; kk < 4; kk++) {
                const int k0 = kk * 16 + kb;
                bh[nf][kk][0] = packh2(we[(k0 + 0) * NH + nf * 8 + n],
                                       we[(k0 + 1) * NH + nf * 8 + n]);
                bh[nf][kk][1] = packh2(we[(k0 + 8) * NH + nf * 8 + n],
                                       we[(k0 + 9) * NH + nf * 8 + n]);
            }
        }
    }
    __syncthreads();

    const int rl = (lane & 7) + ((lane >> 3) & 1) * 8;
    const uint32_t pb  = (uint32_t)(rl * 128 + ((lane >> 4) * 16));
    const uint32_t swt = ((uint32_t)(rl * 128) >> 3) & 0x70;
    const int crow = tid >> 4;          // convert: base row
    const int cc4  = tid & 15;          // convert: fixed 16B column chunk
    const float4* bwp = (const float4*)(smem + OFF_BW) + wid * 32 + (lane & 3);

    for (int tile = blockIdx.x; tile < NTILES; tile += GRID) {
        const int rowBase = tile * TILE_M;

        // ---- convert: LDG.128 -> regs -> fp16 SW128 XHI (+ transposed fp32 S) ----
        #pragma unroll
        for (int w = 0; w < 8; w++) {
            int row = crow + w * 16;
            const float4* src = (cc4 < 8)
                ? (const float4*)(A + (rowBase + row) * 32) + cc4
                : (const float4*)(S + (rowBase + row) * 32) + (cc4 - 8);
            float4 v = *src;
            uint2 hp;
            hp.x = cvth2(v.x, v.y);
            hp.y = cvth2(v.z, v.w);
            *(uint2*)(smem + OFF_XHI + SW((uint32_t)(row * 128 + cc4 * 8))) = hp;
            if (cc4 >= 8) {
                int k = (cc4 - 8) * 4;
                smf[OFF_ST / 4 + (k + 0) * 129 + row] = v.x;
                smf[OFF_ST / 4 + (k + 1) * 129 + row] = v.y;
                smf[OFF_ST / 4 + (k + 2) * 129 + row] = v.z;
                smf[OFF_ST / 4 + (k + 3) * 129 + row] = v.w;
            }
        }
        __syncthreads();   // barrier 1: XHI + ST ready

        // ---- gating MLP: warps 0-3, one full row per thread (from ST, fp32) ----
        if (tid < TILE_M) {
            ull h2[16];
            #pragma unroll
            for (int p = 0; p < 16; p++)
                h2[p] = *(const ull*)(smf + OFF_GB1 / 4 + 2 * p);
            #pragma unroll 4
            for (int k = 0; k < GHID; k++) {
                float sv = smf[OFF_ST / 4 + k * 129 + tid];
                ull s2 = pack2(sv, sv);
                const ulonglong2* wr = (const ulonglong2*)(smem + OFF_GW1 + k * 128);
                #pragma unroll
                for (int j = 0; j < 8; j++) {
                    ulonglong2 w = wr[j];
                    h2[2 * j]     = fma2(s2, w.x, h2[2 * j]);
                    h2[2 * j + 1] = fma2(s2, w.y, h2[2 * j + 1]);
                }
            }
            ull l2[4];
            {
                ulonglong2 b = *(const ulonglong2*)(smem + OFF_GB2);
                l2[0] = b.x; l2[1] = b.y;
                b = *(const ulonglong2*)(smem + OFF_GB2 + 16);
                l2[2] = b.x; l2[3] = b.y;
            }
            #pragma unroll
            for (int p = 0; p < 16; p++) {
                float a, b; unpack2(h2[p], a, b);
                a = fmaxf(a, 0.f); b = fmaxf(b, 0.f);
                ull pa = pack2(a, a), pb2 = pack2(b, b);
                ulonglong2 wa0 = *(const ulonglong2*)(smem + OFF_GW2 + (2 * p) * 32);
                ulonglong2 wa1 = *(const ulonglong2*)(smem + OFF_GW2 + (2 * p) * 32 + 16);
                ulonglong2 wb0 = *(const ulonglong2*)(smem + OFF_GW2 + (2 * p + 1) * 32);
                ulonglong2 wb1 = *(const ulonglong2*)(smem + OFF_GW2 + (2 * p + 1) * 32 + 16);
                l2[0] = fma2(pa, wa0.x, l2[0]); l2[1] = fma2(pa, wa0.y, l2[1]);
                l2[2] = fma2(pa, wa1.x, l2[2]); l2[3] = fma2(pa, wa1.y, l2[3]);
                l2[0] = fma2(pb2, wb0.x, l2[0]); l2[1] = fma2(pb2, wb0.y, l2[1]);
                l2[2] = fma2(pb2, wb1.x, l2[2]); l2[3] = fma2(pb2, wb1.y, l2[3]);
            }
            float logit[NE];
            #pragma unroll
            for (int e2 = 0; e2 < 4; e2++) unpack2(l2[e2], logit[2 * e2], logit[2 * e2 + 1]);
            float mx = logit[0];
            #pragma unroll
            for (int e = 1; e < NE; e++) mx = fmaxf(mx, logit[e]);
            float se = 0.f, pr[NE];
            #pragma unroll
            for (int e = 0; e < NE; e++) { pr[e] = __expf(logit[e] - mx); se += pr[e]; }
            float inv = __fdividef(1.f, se);
            #pragma unroll
            for (int e = 0; e < NE; e++) smf[OFF_PROB / 4 + tid * 9 + e] = pr[e] * inv;
        }

        // ---- expert GEMM: single fp16 product, warp = expert ----
        #pragma unroll 1
        for (int sub = 0; sub < NSUB; sub++) {
            float c[8][4];
            float w2r[8][2];
            #pragma unroll
            for (int nf = 0; nf < 8; nf++) {
                float4 bw = bwp[nf * 4];
                c[nf][0] = bw.x; c[nf][1] = bw.y; c[nf][2] = bw.x; c[nf][3] = bw.y;
                w2r[nf][0] = bw.z; w2r[nf][1] = bw.w;
            }
            #pragma unroll
            for (int kk = 0; kk < 4; kk++) {
                uint32_t ah[4];
                uint32_t off = (uint32_t)(sub * 2048) + ((pb + kk * 32) ^ swt);
                ldsm4(ah, sbase + OFF_XHI + off);
                #pragma unroll
                for (int nf = 0; nf < 8; nf++) mma16816(c[nf], ah, bh[nf][kk][0], bh[nf][kk][1]);
            }
            float p0 = 0.f, p1 = 0.f;
            #pragma unroll
            for (int nf = 0; nf < 8; nf++) {
                p0 = fmaf(fmaxf(c[nf][0], 0.f), w2r[nf][0], p0);
                p0 = fmaf(fmaxf(c[nf][1], 0.f), w2r[nf][1], p0);
                p1 = fmaf(fmaxf(c[nf][2], 0.f), w2r[nf][0], p1);
                p1 = fmaf(fmaxf(c[nf][3], 0.f), w2r[nf][1], p1);
            }
            p0 += __shfl_xor_sync(0xFFFFFFFFu, p0, 1);
            p0 += __shfl_xor_sync(0xFFFFFFFFu, p0, 2);
            p1 += __shfl_xor_sync(0xFFFFFFFFu, p1, 1);
            p1 += __shfl_xor_sync(0xFFFFFFFFu, p1, 2);
            if ((lane & 3) == 0) {
                int r = sub * 16 + (lane >> 2);
                smf[OFF_EO / 4 + r * 9 + wid]       = p0 + b2v;
                smf[OFF_EO / 4 + (r + 8) * 9 + wid] = p1 + b2v;
            }
        }
        __syncthreads();   // barrier 2: EO + PROB ready

        // ---- final: weighted sum over experts ----
        if (tid < TILE_M) {
            const float* pr = smf + OFF_PROB / 4 + tid * 9;
            const float* eo = smf + OFF_EO / 4 + tid * 9;
            float r = 0.f;
            #pragma unroll
            for (int e = 0; e < NE; e++) r = fmaf(pr[e], eo[e], r);
            out[rowBase + tid] = r;
        }
    }
}

extern "C" void kernel_launch(void* const* d_in, const int* in_sizes, int n_in,
                              void* d_out, int out_size)
{
    (void)in_sizes; (void)n_in; (void)out_size;
    const float* A   = (const float*)d_in[0];
    const float* S   = (const float*)d_in[1];
    const float* gw1 = (const float*)d_in[2];
    const float* gb1 = (const float*)d_in[3];
    const float* gw2 = (const float*)d_in[4];
    const float* gb2 = (const float*)d_in[5];
    const float* ew1 = (const float*)d_in[6];
    const float* eb1 = (const float*)d_in[7];
    const float* ew2 = (const float*)d_in[8];
    const float* eb2 = (const float*)d_in[9];
    float* out = (float*)d_out;

    cudaFuncSetAttribute(moe_mma_kernel, cudaFuncAttributeMaxDynamicSharedMemorySize, SMEM_BYTES);
    moe_mma_kernel<<<GRID, THREADS, SMEM_BYTES>>>(
        A, S, gw1, gb1, gw2, gb2, ew1, eb1, ew2, eb2, out);
}